// round 4
// baseline (speedup 1.0000x reference)
#include <cuda_runtime.h>
#include <cuda_bf16.h>

// EdgewiseEnergySum: out[c] += eng[e] * scales[species[c], species[n]] * 0.125
// R4: 8 edges/thread (front-batched 128-bit streaming loads with .cs hints to
// keep out[] + its atomic sectors L2-resident), nibble-packed species table in
// smem (50KB -> 4 CTAs/SM).

#define N_NODES   100000
#define N_BYTES   50000            // 2 species per byte; 50000 % 16 == 0
#define N_EDGES   6400000

__device__ unsigned char g_species4[N_BYTES];

// Kernel 1: zero the poisoned output and pack species into nibbles.
__global__ void prep_kernel(const int* __restrict__ atom_type,
                            float* __restrict__ out, int n) {
    int i = blockIdx.x * blockDim.x + threadIdx.x;
    if (i < n) out[i] = 0.0f;
    if (i < N_BYTES) {
        unsigned lo = (unsigned)atom_type[2 * i];
        unsigned hi = (unsigned)atom_type[2 * i + 1];
        g_species4[i] = (unsigned char)(lo | (hi << 4));
    }
}

__device__ __forceinline__ int nib(const unsigned char* t, int idx) {
    unsigned b = t[idx >> 1];
    return (int)((b >> ((idx & 1) << 2)) & 7u);
}

// Kernel 2: persistent scatter, 4 CTAs/SM, 8 edges per thread-iteration.
__global__ __launch_bounds__(512, 4) void edgewise_scatter_kernel(
    const int* __restrict__ centers,
    const int* __restrict__ neighbors,
    const float* __restrict__ eng,
    const float* __restrict__ scales,
    float* __restrict__ out)
{
    __shared__ float s_sc[64];
    extern __shared__ unsigned char s_sp[];

    if (threadIdx.x < 64) s_sc[threadIdx.x] = scales[threadIdx.x] * 0.125f;

    // cooperative 128-bit copy: 50000/16 = 3125 uint4
    {
        const uint4* src = reinterpret_cast<const uint4*>(g_species4);
        uint4*       dst = reinterpret_cast<uint4*>(s_sp);
        for (int i = threadIdx.x; i < N_BYTES / 16; i += blockDim.x)
            dst[i] = src[i];
    }
    __syncthreads();

    const int ngroups = N_EDGES / 8;           // 800,000 groups of 8 edges
    const int stride  = gridDim.x * blockDim.x;

    const int4*   c_v = reinterpret_cast<const int4*>(centers);
    const int4*   n_v = reinterpret_cast<const int4*>(neighbors);
    const float4* e_v = reinterpret_cast<const float4*>(eng);

    for (int i = blockIdx.x * blockDim.x + threadIdx.x; i < ngroups; i += stride) {
        // front-batched streaming loads: 6 x LDG.128 with evict-first hint
        int4   ca = __ldcs(&c_v[2 * i]);
        int4   cb = __ldcs(&c_v[2 * i + 1]);
        int4   na = __ldcs(&n_v[2 * i]);
        int4   nb = __ldcs(&n_v[2 * i + 1]);
        float4 ea = __ldcs(&e_v[2 * i]);
        float4 eb = __ldcs(&e_v[2 * i + 1]);

        float v0 = ea.x * s_sc[(nib(s_sp, ca.x) << 3) | nib(s_sp, na.x)];
        float v1 = ea.y * s_sc[(nib(s_sp, ca.y) << 3) | nib(s_sp, na.y)];
        float v2 = ea.z * s_sc[(nib(s_sp, ca.z) << 3) | nib(s_sp, na.z)];
        float v3 = ea.w * s_sc[(nib(s_sp, ca.w) << 3) | nib(s_sp, na.w)];
        float v4 = eb.x * s_sc[(nib(s_sp, cb.x) << 3) | nib(s_sp, nb.x)];
        float v5 = eb.y * s_sc[(nib(s_sp, cb.y) << 3) | nib(s_sp, nb.y)];
        float v6 = eb.z * s_sc[(nib(s_sp, cb.z) << 3) | nib(s_sp, nb.z)];
        float v7 = eb.w * s_sc[(nib(s_sp, cb.w) << 3) | nib(s_sp, nb.w)];

        atomicAdd(&out[ca.x], v0);
        atomicAdd(&out[ca.y], v1);
        atomicAdd(&out[ca.z], v2);
        atomicAdd(&out[ca.w], v3);
        atomicAdd(&out[cb.x], v4);
        atomicAdd(&out[cb.y], v5);
        atomicAdd(&out[cb.z], v6);
        atomicAdd(&out[cb.w], v7);
    }
}

extern "C" void kernel_launch(void* const* d_in, const int* in_sizes, int n_in,
                              void* d_out, int out_size) {
    const int*   edge_index = (const int*)d_in[0];      // [2, E]
    const float* edge_eng   = (const float*)d_in[1];    // [E]
    const int*   atom_type  = (const int*)d_in[2];      // [N]
    const float* scales     = (const float*)d_in[3];    // [8, 8]
    float* out = (float*)d_out;

    const int E = in_sizes[0] / 2;   // 6,400,000
    const int N = out_size;          // 100,000

    prep_kernel<<<(N + 255) / 256, 256>>>(atom_type, out, N);

    const int* centers   = edge_index;
    const int* neighbors = edge_index + E;

    const int smem_bytes = N_BYTES;  // 50,000 bytes dynamic shared
    static int attr_set = 0;
    if (!attr_set) {
        cudaFuncSetAttribute(edgewise_scatter_kernel,
                             cudaFuncAttributeMaxDynamicSharedMemorySize,
                             smem_bytes);
        attr_set = 1;
    }

    // 4 blocks per SM x 148 SMs = 592 blocks, 512 threads each
    edgewise_scatter_kernel<<<592, 512, smem_bytes>>>(
        centers, neighbors, edge_eng, scales, out);
}